// round 1
// baseline (speedup 1.0000x reference)
#include <cuda_runtime.h>
#include <math.h>

#define N0 2048
#define N1 1024

// Scratch (allocation-free rule: __device__ globals)
__device__ float  g_kn0[N0 * 9];
__device__ float  g_inv0[N0 * 9];
__device__ float  g_kn1[N1 * 25];
__device__ float  g_inv1[N1 * 25];
__device__ double g_acc0;
__device__ double g_acc1;

// ---------------------------------------------------------------------------
// Prep layer 0: normalize + 3x3 inverse via adjugate (all registers)
// ---------------------------------------------------------------------------
__global__ void prep3_kernel(const float* __restrict__ in) {
    int i = blockIdx.x * blockDim.x + threadIdx.x;
    if (i == 0) { g_acc0 = 0.0; g_acc1 = 0.0; }
    if (i >= N0) return;

    float a[9];
    float ss = 0.f;
#pragma unroll
    for (int k = 0; k < 9; k++) { a[k] = in[i * 9 + k]; ss += a[k] * a[k]; }
    float inv_n = 1.0f / (sqrtf(ss) + 1e-8f);
#pragma unroll
    for (int k = 0; k < 9; k++) a[k] *= inv_n;

    float c00 = a[4] * a[8] - a[5] * a[7];
    float c01 = a[5] * a[6] - a[3] * a[8];
    float c02 = a[3] * a[7] - a[4] * a[6];
    float det = a[0] * c00 + a[1] * c01 + a[2] * c02;
    float id  = 1.0f / det;

    float v[9];
    v[0] = c00 * id;
    v[1] = (a[2] * a[7] - a[1] * a[8]) * id;
    v[2] = (a[1] * a[5] - a[2] * a[4]) * id;
    v[3] = c01 * id;
    v[4] = (a[0] * a[8] - a[2] * a[6]) * id;
    v[5] = (a[2] * a[3] - a[0] * a[5]) * id;
    v[6] = c02 * id;
    v[7] = (a[1] * a[6] - a[0] * a[7]) * id;
    v[8] = (a[0] * a[4] - a[1] * a[3]) * id;

#pragma unroll
    for (int k = 0; k < 9; k++) {
        g_kn0[i * 9 + k]  = a[k];
        g_inv0[i * 9 + k] = v[k];
    }
}

// ---------------------------------------------------------------------------
// Prep layer 1: normalize + 5x5 inverse via Gauss-Jordan w/ partial pivoting
// (local-memory arrays; only 1024 threads total -> negligible cost)
// ---------------------------------------------------------------------------
__global__ void prep5_kernel(const float* __restrict__ in) {
    int i = blockIdx.x * blockDim.x + threadIdx.x;
    if (i >= N1) return;

    float m[5][10];
    float ss = 0.f;
    for (int r = 0; r < 5; r++)
        for (int c = 0; c < 5; c++) {
            float x = in[i * 25 + r * 5 + c];
            m[r][c] = x;
            ss += x * x;
            m[r][c + 5] = (r == c) ? 1.0f : 0.0f;
        }
    float inv_n = 1.0f / (sqrtf(ss) + 1e-8f);
    for (int r = 0; r < 5; r++)
        for (int c = 0; c < 5; c++) {
            m[r][c] *= inv_n;
            g_kn1[i * 25 + r * 5 + c] = m[r][c];
        }

    for (int col = 0; col < 5; col++) {
        // partial pivot
        int p = col;
        float best = fabsf(m[col][col]);
        for (int r = col + 1; r < 5; r++) {
            float v = fabsf(m[r][col]);
            if (v > best) { best = v; p = r; }
        }
        if (p != col) {
            for (int c = 0; c < 10; c++) {
                float t = m[col][c]; m[col][c] = m[p][c]; m[p][c] = t;
            }
        }
        float piv = 1.0f / m[col][col];
        for (int c = col; c < 10; c++) m[col][c] *= piv;
        for (int r = 0; r < 5; r++) {
            if (r == col) continue;
            float f = m[r][col];
            for (int c = col; c < 10; c++) m[r][c] -= f * m[col][c];
        }
    }

    for (int r = 0; r < 5; r++)
        for (int c = 0; c < 5; c++)
            g_inv1[i * 25 + r * 5 + c] = m[r][c + 5];
}

// ---------------------------------------------------------------------------
// Pair kernel: for tile (by, bx) with by >= bx, each thread computes one
// (i, j) pair with i > j:  relu(1 - ||I - inv[i] @ kn[j]||_F)
// ---------------------------------------------------------------------------
template <int LAYER>
__global__ void pair_kernel() {
    constexpr int D  = (LAYER == 0) ? 3 : 5;
    constexpr int N  = (LAYER == 0) ? N0 : N1;
    constexpr int DD = D * D;
    constexpr int T  = 16;

    const float* __restrict__ kn  = (LAYER == 0) ? g_kn0  : g_kn1;
    const float* __restrict__ inv = (LAYER == 0) ? g_inv0 : g_inv1;

    int bx = blockIdx.x, by = blockIdx.y;
    if (by < bx) return;  // strict upper tiles have no i>j pairs

    __shared__ float sInv[T][DD];
    __shared__ float sKn[T][DD];

    int tid = threadIdx.y * T + threadIdx.x;
    int i0 = by * T, j0 = bx * T;

    for (int t = tid; t < T * DD; t += T * T) {
        int row = t / DD, c = t % DD;
        sInv[row][c] = inv[(i0 + row) * DD + c];
        sKn[row][c]  = kn[(j0 + row) * DD + c];
    }
    __syncthreads();

    int i = i0 + threadIdx.y;
    int j = j0 + threadIdx.x;

    float val = 0.0f;
    if (i > j && i < N) {
        float s = 0.0f;
#pragma unroll
        for (int r = 0; r < D; r++) {
#pragma unroll
            for (int c = 0; c < D; c++) {
                float acc = 0.0f;
#pragma unroll
                for (int k = 0; k < D; k++)
                    acc += sInv[threadIdx.y][r * D + k] * sKn[threadIdx.x][k * D + c];
                float t = ((r == c) ? 1.0f : 0.0f) - acc;
                s += t * t;
            }
        }
        float e = sqrtf(s);
        val = fmaxf(0.0f, 1.0f - e);
    }

    // block reduction: warp shuffle then cross-warp via shared
#pragma unroll
    for (int o = 16; o > 0; o >>= 1)
        val += __shfl_down_sync(0xffffffffu, val, o);

    __shared__ float wsum[T * T / 32];
    if ((tid & 31) == 0) wsum[tid >> 5] = val;
    __syncthreads();
    if (tid == 0) {
        float s = 0.0f;
#pragma unroll
        for (int w = 0; w < T * T / 32; w++) s += wsum[w];
        if (s != 0.0f)
            atomicAdd((LAYER == 0) ? &g_acc0 : &g_acc1, (double)s);
    }
}

// ---------------------------------------------------------------------------
// Finalize: combine accumulators into the scalar loss
// ---------------------------------------------------------------------------
__global__ void finalize_kernel(float* __restrict__ out) {
    double l0 = 2.0 * g_acc0 / ((double)N0 * (double)(N0 - 1));
    double l1 = 2.0 * g_acc1 / ((double)N1 * (double)(N1 - 1));
    out[0] = (float)(0.5 * (l0 + l1));
}

extern "C" void kernel_launch(void* const* d_in, const int* in_sizes, int n_in,
                              void* d_out, int out_size) {
    const float* k0 = (const float*)d_in[0];
    const float* k1 = (const float*)d_in[1];
    float* out = (float*)d_out;

    prep3_kernel<<<(N0 + 255) / 256, 256>>>(k0);
    prep5_kernel<<<(N1 + 127) / 128, 128>>>(k1);

    dim3 blk(16, 16);
    dim3 g0(N0 / 16, N0 / 16);
    dim3 g1(N1 / 16, N1 / 16);
    pair_kernel<0><<<g0, blk>>>();
    pair_kernel<1><<<g1, blk>>>();

    finalize_kernel<<<1, 1>>>(out);
}